// round 14
// baseline (speedup 1.0000x reference)
#include <cuda_runtime.h>
#include <cuda_bf16.h>
#include <cstdint>

#define IMG_H 256
#define IMG_W 256
#define ROWS_PER_THREAD 16
#define FULLMASK 0xffffffffu

struct Row { float4 m; float lx, ly, r; };

__device__ __forceinline__ void stcs4(float* p, float4 v) {
    asm volatile("st.global.cs.v4.f32 [%0], {%1,%2,%3,%4};"
                 :: "l"(p), "f"(v.x), "f"(v.y), "f"(v.z), "f"(v.w) : "memory");
}

__device__ __forceinline__ float4 ldgnc4(const float* p) {
    float4 v;
    asm volatile("ld.global.nc.v4.f32 {%0,%1,%2,%3}, [%4];"
                 : "=f"(v.x), "=f"(v.y), "=f"(v.z), "=f"(v.w) : "l"(p));
    return v;
}

// Register-rolling separable 4x4 depthwise blur (R13 champion, 5 CTAs/SM probe).
// Warp-shuffle halo: each warp owns a 128-col segment; per row each thread
// does one float4 LDG (nc path); halos via shfl; streaming stores.
// out[y,x] = sum_{a,b} k[a][b] * in[y+1-a, x+1-b]   (zero pad outside)
__global__ __launch_bounds__(256, 5)
void Blur2_kernel(const float* __restrict__ in,
                  const float* __restrict__ kern,
                  float* __restrict__ out) {
    const int t     = threadIdx.x;
    const int lane  = t & 31;
    const int warp  = t >> 5;           // 0..7
    const int seg   = warp & 1;         // column segment: 0 or 1
    const int strip = warp >> 1;        // 0..3
    const int xg    = seg * 128 + lane * 4;
    const int z     = blockIdx.y;       // n*c fold (1024)
    const int y0    = blockIdx.x * 64 + strip * ROWS_PER_THREAD;

    const float* __restrict__ base  = in  + (size_t)z * (IMG_H * IMG_W);
    float*       __restrict__ obase = out + (size_t)z * (IMG_H * IMG_W);

    // separable factors (rank-1 kernel)
    const float w0 = kern[0], w1 = kern[1], w2 = kern[2], w3 = kern[3];
    const float rk = 1.0f / w0;
    const float u1 = kern[4] * rk, u2 = kern[8] * rk, u3 = kern[12] * rk;

    const bool left_edge_load  = (lane == 0)  && (seg == 1);
    const bool right_edge_load = (lane == 31) && (seg == 0);

    auto loadrow = [&](int gy) -> Row {
        Row v;
        v.m = make_float4(0.f, 0.f, 0.f, 0.f);
        v.lx = 0.f; v.ly = 0.f; v.r = 0.f;
        if ((unsigned)gy < (unsigned)IMG_H) {
            const float* rp = base + gy * IMG_W + xg;
            v.m = ldgnc4(rp);
            if (left_edge_load)  { const float2 e = *(const float2*)(rp - 2); v.lx = e.x; v.ly = e.y; }
            if (right_edge_load) { v.r = rp[4]; }
        }
        return v;
    };

    auto hcalc = [&](const Row& v) -> float4 {
        float cm2 = __shfl_up_sync(FULLMASK, v.m.z, 1);
        float cm1 = __shfl_up_sync(FULLMASK, v.m.w, 1);
        float p4  = __shfl_down_sync(FULLMASK, v.m.x, 1);
        if (lane == 0)  { cm2 = v.lx; cm1 = v.ly; }
        if (lane == 31) { p4 = v.r; }
        float4 h;
        h.x = fmaf(w3, cm2,   fmaf(w2, cm1,   fmaf(w1, v.m.x, w0 * v.m.y)));
        h.y = fmaf(w3, cm1,   fmaf(w2, v.m.x, fmaf(w1, v.m.y, w0 * v.m.z)));
        h.z = fmaf(w3, v.m.x, fmaf(w2, v.m.y, fmaf(w1, v.m.z, w0 * v.m.w)));
        h.w = fmaf(w3, v.m.y, fmaf(w2, v.m.z, fmaf(w1, v.m.w, w0 * p4)));
        return h;
    };

    // prologue: rows y0-2, y0-1, y0
    Row p0 = loadrow(y0 - 2);
    Row p1 = loadrow(y0 - 1);
    Row p2 = loadrow(y0);
    float4 h0 = hcalc(p0);
    float4 h1 = hcalc(p1);
    float4 h2 = hcalc(p2);

    #pragma unroll
    for (int i = 0; i < ROWS_PER_THREAD; i += 4) {
        // batch independent LDGs for the next 4 rows
        Row a = loadrow(y0 + 1 + i);
        Row b = loadrow(y0 + 2 + i);
        Row c = loadrow(y0 + 3 + i);
        Row d = loadrow(y0 + 4 + i);

        float* op = obase + (y0 + i) * IMG_W + xg;

        float4 h3 = hcalc(a);
        float4 o;
        o.x = fmaf(u3, h0.x, fmaf(u2, h1.x, fmaf(u1, h2.x, h3.x)));
        o.y = fmaf(u3, h0.y, fmaf(u2, h1.y, fmaf(u1, h2.y, h3.y)));
        o.z = fmaf(u3, h0.z, fmaf(u2, h1.z, fmaf(u1, h2.z, h3.z)));
        o.w = fmaf(u3, h0.w, fmaf(u2, h1.w, fmaf(u1, h2.w, h3.w)));
        stcs4(op, o);

        float4 h4 = hcalc(b);
        o.x = fmaf(u3, h1.x, fmaf(u2, h2.x, fmaf(u1, h3.x, h4.x)));
        o.y = fmaf(u3, h1.y, fmaf(u2, h2.y, fmaf(u1, h3.y, h4.y)));
        o.z = fmaf(u3, h1.z, fmaf(u2, h2.z, fmaf(u1, h3.z, h4.z)));
        o.w = fmaf(u3, h1.w, fmaf(u2, h2.w, fmaf(u1, h3.w, h4.w)));
        stcs4(op + IMG_W, o);

        float4 h5 = hcalc(c);
        o.x = fmaf(u3, h2.x, fmaf(u2, h3.x, fmaf(u1, h4.x, h5.x)));
        o.y = fmaf(u3, h2.y, fmaf(u2, h3.y, fmaf(u1, h4.y, h5.y)));
        o.z = fmaf(u3, h2.z, fmaf(u2, h3.z, fmaf(u1, h4.z, h5.z)));
        o.w = fmaf(u3, h2.w, fmaf(u2, h3.w, fmaf(u1, h4.w, h5.w)));
        stcs4(op + 2 * IMG_W, o);

        float4 h6 = hcalc(d);
        o.x = fmaf(u3, h3.x, fmaf(u2, h4.x, fmaf(u1, h5.x, h6.x)));
        o.y = fmaf(u3, h3.y, fmaf(u2, h4.y, fmaf(u1, h5.y, h6.y)));
        o.z = fmaf(u3, h3.z, fmaf(u2, h4.z, fmaf(u1, h5.z, h6.z)));
        o.w = fmaf(u3, h3.w, fmaf(u2, h4.w, fmaf(u1, h5.w, h6.w)));
        stcs4(op + 3 * IMG_W, o);

        h0 = h4; h1 = h5; h2 = h6;
    }
}

extern "C" void kernel_launch(void* const* d_in, const int* in_sizes, int n_in,
                              void* d_out, int out_size) {
    int xi = 0, ki = 1;
    if (n_in >= 2 && in_sizes[0] == 16) { xi = 1; ki = 0; }
    const float* x = (const float*)d_in[xi];
    const float* k = (const float*)d_in[ki];
    float* o       = (float*)d_out;

    const int nc = in_sizes[xi] / (IMG_H * IMG_W);   // 1024
    dim3 grid(IMG_H / 64, nc);                        // (4, 1024)
    dim3 block(256);
    Blur2_kernel<<<grid, block>>>(x, k, o);
}

// round 15
// speedup vs baseline: 1.0197x; 1.0197x over previous
#include <cuda_runtime.h>
#include <cuda_bf16.h>
#include <cstdint>

#define IMG_H 256
#define IMG_W 256
#define ROWS_PER_THREAD 16
#define FULLMASK 0xffffffffu

struct Row { float4 m; float lx, ly, r; };

__device__ __forceinline__ void stcs4(float* p, float4 v) {
    asm volatile("st.global.cs.v4.f32 [%0], {%1,%2,%3,%4};"
                 :: "l"(p), "f"(v.x), "f"(v.y), "f"(v.z), "f"(v.w) : "memory");
}

__device__ __forceinline__ float4 ldgnc4(const float* p) {
    float4 v;
    asm volatile("ld.global.nc.v4.f32 {%0,%1,%2,%3}, [%4];"
                 : "=f"(v.x), "=f"(v.y), "=f"(v.z), "=f"(v.w) : "l"(p));
    return v;
}

// Register-rolling separable 4x4 depthwise blur (final champion).
// - rank-1 kernel factorization: 16 taps -> 4+4 separable taps
// - warp-shuffle halo: one float4 nc-LDG per thread per row, halos via shfl
// - 4-row load batching for MLP; streaming (evict-first) float4 stores
// - 32 warps/SM at regs=60: measured optimum of the warps x burst frontier
// out[y,x] = sum_{a,b} k[a][b] * in[y+1-a, x+1-b]   (zero pad outside)
__global__ __launch_bounds__(256)
void Blur2_kernel(const float* __restrict__ in,
                  const float* __restrict__ kern,
                  float* __restrict__ out) {
    const int t     = threadIdx.x;
    const int lane  = t & 31;
    const int warp  = t >> 5;           // 0..7
    const int seg   = warp & 1;         // column segment: 0 or 1
    const int strip = warp >> 1;        // 0..3
    const int xg    = seg * 128 + lane * 4;
    const int z     = blockIdx.y;       // n*c fold (1024)
    const int y0    = blockIdx.x * 64 + strip * ROWS_PER_THREAD;

    const float* __restrict__ base  = in  + (size_t)z * (IMG_H * IMG_W);
    float*       __restrict__ obase = out + (size_t)z * (IMG_H * IMG_W);

    // separable factors (rank-1 kernel)
    const float w0 = kern[0], w1 = kern[1], w2 = kern[2], w3 = kern[3];
    const float rk = 1.0f / w0;
    const float u1 = kern[4] * rk, u2 = kern[8] * rk, u3 = kern[12] * rk;

    const bool left_edge_load  = (lane == 0)  && (seg == 1);
    const bool right_edge_load = (lane == 31) && (seg == 0);

    auto loadrow = [&](int gy) -> Row {
        Row v;
        v.m = make_float4(0.f, 0.f, 0.f, 0.f);
        v.lx = 0.f; v.ly = 0.f; v.r = 0.f;
        if ((unsigned)gy < (unsigned)IMG_H) {
            const float* rp = base + gy * IMG_W + xg;
            v.m = ldgnc4(rp);
            if (left_edge_load)  { const float2 e = *(const float2*)(rp - 2); v.lx = e.x; v.ly = e.y; }
            if (right_edge_load) { v.r = rp[4]; }
        }
        return v;
    };

    auto hcalc = [&](const Row& v) -> float4 {
        float cm2 = __shfl_up_sync(FULLMASK, v.m.z, 1);
        float cm1 = __shfl_up_sync(FULLMASK, v.m.w, 1);
        float p4  = __shfl_down_sync(FULLMASK, v.m.x, 1);
        if (lane == 0)  { cm2 = v.lx; cm1 = v.ly; }
        if (lane == 31) { p4 = v.r; }
        float4 h;
        h.x = fmaf(w3, cm2,   fmaf(w2, cm1,   fmaf(w1, v.m.x, w0 * v.m.y)));
        h.y = fmaf(w3, cm1,   fmaf(w2, v.m.x, fmaf(w1, v.m.y, w0 * v.m.z)));
        h.z = fmaf(w3, v.m.x, fmaf(w2, v.m.y, fmaf(w1, v.m.z, w0 * v.m.w)));
        h.w = fmaf(w3, v.m.y, fmaf(w2, v.m.z, fmaf(w1, v.m.w, w0 * p4)));
        return h;
    };

    // prologue: rows y0-2, y0-1, y0
    Row p0 = loadrow(y0 - 2);
    Row p1 = loadrow(y0 - 1);
    Row p2 = loadrow(y0);
    float4 h0 = hcalc(p0);
    float4 h1 = hcalc(p1);
    float4 h2 = hcalc(p2);

    #pragma unroll
    for (int i = 0; i < ROWS_PER_THREAD; i += 4) {
        // batch independent LDGs for the next 4 rows
        Row a = loadrow(y0 + 1 + i);
        Row b = loadrow(y0 + 2 + i);
        Row c = loadrow(y0 + 3 + i);
        Row d = loadrow(y0 + 4 + i);

        float* op = obase + (y0 + i) * IMG_W + xg;

        float4 h3 = hcalc(a);
        float4 o;
        o.x = fmaf(u3, h0.x, fmaf(u2, h1.x, fmaf(u1, h2.x, h3.x)));
        o.y = fmaf(u3, h0.y, fmaf(u2, h1.y, fmaf(u1, h2.y, h3.y)));
        o.z = fmaf(u3, h0.z, fmaf(u2, h1.z, fmaf(u1, h2.z, h3.z)));
        o.w = fmaf(u3, h0.w, fmaf(u2, h1.w, fmaf(u1, h2.w, h3.w)));
        stcs4(op, o);

        float4 h4 = hcalc(b);
        o.x = fmaf(u3, h1.x, fmaf(u2, h2.x, fmaf(u1, h3.x, h4.x)));
        o.y = fmaf(u3, h1.y, fmaf(u2, h2.y, fmaf(u1, h3.y, h4.y)));
        o.z = fmaf(u3, h1.z, fmaf(u2, h2.z, fmaf(u1, h3.z, h4.z)));
        o.w = fmaf(u3, h1.w, fmaf(u2, h2.w, fmaf(u1, h3.w, h4.w)));
        stcs4(op + IMG_W, o);

        float4 h5 = hcalc(c);
        o.x = fmaf(u3, h2.x, fmaf(u2, h3.x, fmaf(u1, h4.x, h5.x)));
        o.y = fmaf(u3, h2.y, fmaf(u2, h3.y, fmaf(u1, h4.y, h5.y)));
        o.z = fmaf(u3, h2.z, fmaf(u2, h3.z, fmaf(u1, h4.z, h5.z)));
        o.w = fmaf(u3, h2.w, fmaf(u2, h3.w, fmaf(u1, h4.w, h5.w)));
        stcs4(op + 2 * IMG_W, o);

        float4 h6 = hcalc(d);
        o.x = fmaf(u3, h3.x, fmaf(u2, h4.x, fmaf(u1, h5.x, h6.x)));
        o.y = fmaf(u3, h3.y, fmaf(u2, h4.y, fmaf(u1, h5.y, h6.y)));
        o.z = fmaf(u3, h3.z, fmaf(u2, h4.z, fmaf(u1, h5.z, h6.z)));
        o.w = fmaf(u3, h3.w, fmaf(u2, h4.w, fmaf(u1, h5.w, h6.w)));
        stcs4(op + 3 * IMG_W, o);

        h0 = h4; h1 = h5; h2 = h6;
    }
}

extern "C" void kernel_launch(void* const* d_in, const int* in_sizes, int n_in,
                              void* d_out, int out_size) {
    int xi = 0, ki = 1;
    if (n_in >= 2 && in_sizes[0] == 16) { xi = 1; ki = 0; }
    const float* x = (const float*)d_in[xi];
    const float* k = (const float*)d_in[ki];
    float* o       = (float*)d_out;

    const int nc = in_sizes[xi] / (IMG_H * IMG_W);   // 1024
    dim3 grid(IMG_H / 64, nc);                        // (4, 1024)
    dim3 block(256);
    Blur2_kernel<<<grid, block>>>(x, k, o);
}

// round 16
// speedup vs baseline: 1.0244x; 1.0046x over previous
#include <cuda_runtime.h>
#include <cuda_bf16.h>
#include <cstdint>

#define IMG_H 256
#define IMG_W 256
#define ROWS_PER_THREAD 16
#define FULLMASK 0xffffffffu

struct Row { float4 m; float lx, ly, r; };

__device__ __forceinline__ void stcs4(float* p, float4 v) {
    asm volatile("st.global.cs.v4.f32 [%0], {%1,%2,%3,%4};"
                 :: "l"(p), "f"(v.x), "f"(v.y), "f"(v.z), "f"(v.w) : "memory");
}

__device__ __forceinline__ float4 ldgnc4(const float* p) {
    float4 v;
    asm volatile("ld.global.nc.v4.f32 {%0,%1,%2,%3}, [%4];"
                 : "=f"(v.x), "=f"(v.y), "=f"(v.z), "=f"(v.w) : "l"(p));
    return v;
}

// Register-rolling separable 4x4 depthwise blur (final champion).
// - rank-1 kernel factorization: 16 taps -> 4+4 separable taps
// - warp-shuffle halo: one float4 nc-LDG per thread per row, halos via shfl
// - 4-row load batching for MLP; streaming (evict-first) float4 stores
// - 32 warps/SM at regs=60: measured optimum of the warps x burst frontier
// out[y,x] = sum_{a,b} k[a][b] * in[y+1-a, x+1-b]   (zero pad outside)
__global__ __launch_bounds__(256)
void Blur2_kernel(const float* __restrict__ in,
                  const float* __restrict__ kern,
                  float* __restrict__ out) {
    const int t     = threadIdx.x;
    const int lane  = t & 31;
    const int warp  = t >> 5;           // 0..7
    const int seg   = warp & 1;         // column segment: 0 or 1
    const int strip = warp >> 1;        // 0..3
    const int xg    = seg * 128 + lane * 4;
    const int z     = blockIdx.y;       // n*c fold (1024)
    const int y0    = blockIdx.x * 64 + strip * ROWS_PER_THREAD;

    const float* __restrict__ base  = in  + (size_t)z * (IMG_H * IMG_W);
    float*       __restrict__ obase = out + (size_t)z * (IMG_H * IMG_W);

    // separable factors (rank-1 kernel)
    const float w0 = kern[0], w1 = kern[1], w2 = kern[2], w3 = kern[3];
    const float rk = 1.0f / w0;
    const float u1 = kern[4] * rk, u2 = kern[8] * rk, u3 = kern[12] * rk;

    const bool left_edge_load  = (lane == 0)  && (seg == 1);
    const bool right_edge_load = (lane == 31) && (seg == 0);

    auto loadrow = [&](int gy) -> Row {
        Row v;
        v.m = make_float4(0.f, 0.f, 0.f, 0.f);
        v.lx = 0.f; v.ly = 0.f; v.r = 0.f;
        if ((unsigned)gy < (unsigned)IMG_H) {
            const float* rp = base + gy * IMG_W + xg;
            v.m = ldgnc4(rp);
            if (left_edge_load)  { const float2 e = *(const float2*)(rp - 2); v.lx = e.x; v.ly = e.y; }
            if (right_edge_load) { v.r = rp[4]; }
        }
        return v;
    };

    auto hcalc = [&](const Row& v) -> float4 {
        float cm2 = __shfl_up_sync(FULLMASK, v.m.z, 1);
        float cm1 = __shfl_up_sync(FULLMASK, v.m.w, 1);
        float p4  = __shfl_down_sync(FULLMASK, v.m.x, 1);
        if (lane == 0)  { cm2 = v.lx; cm1 = v.ly; }
        if (lane == 31) { p4 = v.r; }
        float4 h;
        h.x = fmaf(w3, cm2,   fmaf(w2, cm1,   fmaf(w1, v.m.x, w0 * v.m.y)));
        h.y = fmaf(w3, cm1,   fmaf(w2, v.m.x, fmaf(w1, v.m.y, w0 * v.m.z)));
        h.z = fmaf(w3, v.m.x, fmaf(w2, v.m.y, fmaf(w1, v.m.z, w0 * v.m.w)));
        h.w = fmaf(w3, v.m.y, fmaf(w2, v.m.z, fmaf(w1, v.m.w, w0 * p4)));
        return h;
    };

    // prologue: rows y0-2, y0-1, y0
    Row p0 = loadrow(y0 - 2);
    Row p1 = loadrow(y0 - 1);
    Row p2 = loadrow(y0);
    float4 h0 = hcalc(p0);
    float4 h1 = hcalc(p1);
    float4 h2 = hcalc(p2);

    #pragma unroll
    for (int i = 0; i < ROWS_PER_THREAD; i += 4) {
        // batch independent LDGs for the next 4 rows
        Row a = loadrow(y0 + 1 + i);
        Row b = loadrow(y0 + 2 + i);
        Row c = loadrow(y0 + 3 + i);
        Row d = loadrow(y0 + 4 + i);

        float* op = obase + (y0 + i) * IMG_W + xg;

        float4 h3 = hcalc(a);
        float4 o;
        o.x = fmaf(u3, h0.x, fmaf(u2, h1.x, fmaf(u1, h2.x, h3.x)));
        o.y = fmaf(u3, h0.y, fmaf(u2, h1.y, fmaf(u1, h2.y, h3.y)));
        o.z = fmaf(u3, h0.z, fmaf(u2, h1.z, fmaf(u1, h2.z, h3.z)));
        o.w = fmaf(u3, h0.w, fmaf(u2, h1.w, fmaf(u1, h2.w, h3.w)));
        stcs4(op, o);

        float4 h4 = hcalc(b);
        o.x = fmaf(u3, h1.x, fmaf(u2, h2.x, fmaf(u1, h3.x, h4.x)));
        o.y = fmaf(u3, h1.y, fmaf(u2, h2.y, fmaf(u1, h3.y, h4.y)));
        o.z = fmaf(u3, h1.z, fmaf(u2, h2.z, fmaf(u1, h3.z, h4.z)));
        o.w = fmaf(u3, h1.w, fmaf(u2, h2.w, fmaf(u1, h3.w, h4.w)));
        stcs4(op + IMG_W, o);

        float4 h5 = hcalc(c);
        o.x = fmaf(u3, h2.x, fmaf(u2, h3.x, fmaf(u1, h4.x, h5.x)));
        o.y = fmaf(u3, h2.y, fmaf(u2, h3.y, fmaf(u1, h4.y, h5.y)));
        o.z = fmaf(u3, h2.z, fmaf(u2, h3.z, fmaf(u1, h4.z, h5.z)));
        o.w = fmaf(u3, h2.w, fmaf(u2, h3.w, fmaf(u1, h4.w, h5.w)));
        stcs4(op + 2 * IMG_W, o);

        float4 h6 = hcalc(d);
        o.x = fmaf(u3, h3.x, fmaf(u2, h4.x, fmaf(u1, h5.x, h6.x)));
        o.y = fmaf(u3, h3.y, fmaf(u2, h4.y, fmaf(u1, h5.y, h6.y)));
        o.z = fmaf(u3, h3.z, fmaf(u2, h4.z, fmaf(u1, h5.z, h6.z)));
        o.w = fmaf(u3, h3.w, fmaf(u2, h4.w, fmaf(u1, h5.w, h6.w)));
        stcs4(op + 3 * IMG_W, o);

        h0 = h4; h1 = h5; h2 = h6;
    }
}

extern "C" void kernel_launch(void* const* d_in, const int* in_sizes, int n_in,
                              void* d_out, int out_size) {
    int xi = 0, ki = 1;
    if (n_in >= 2 && in_sizes[0] == 16) { xi = 1; ki = 0; }
    const float* x = (const float*)d_in[xi];
    const float* k = (const float*)d_in[ki];
    float* o       = (float*)d_out;

    const int nc = in_sizes[xi] / (IMG_H * IMG_W);   // 1024
    dim3 grid(IMG_H / 64, nc);                        // (4, 1024)
    dim3 block(256);
    Blur2_kernel<<<grid, block>>>(x, k, o);
}